// round 6
// baseline (speedup 1.0000x reference)
#include <cuda_runtime.h>
#include <cuda_bf16.h>
#include <cstdint>

#define B_ 64
#define S_ 2048
#define D_ 512

#define TM 128           // M rows per CTA
#define TN 256           // N cols per CTA (2 CTAs split e-dim)
#define TK 32            // K per stage tile
#define NKT (D_ / TK)    // 16 k-tiles
#define NSCH 8           // context S-chunks

// ---------------- scratch globals ----------------
__device__ float g_wq[B_ * D_];
__device__ float g_scores[B_ * S_];
__device__ float g_spart[2][B_ * S_];
__device__ float g_stats[2 * B_];
__device__ float g_ctx[NSCH][B_ * D_];
// Wc in mma-fragment order: [kb][kk][wc(8)][j2][lane][4]  (tf32 RNA-rounded)
#define BSZ (TK * D_)    // 16384 floats per full k-tile
#define HBSZ (BSZ / 2)   // 8192 floats per half (one CTA's 256 cols)
__device__ __align__(16) float g_wcF[NKT][BSZ];

// ---------------- helpers ----------------
__device__ __forceinline__ float to_tf32(float x) {
    asm("cvt.rna.tf32.f32 %0, %0;" : "+f"(x));
    return x;
}
__device__ __forceinline__ float fast_tanh(float x) {
    float xc = fminf(fmaxf(x, -15.f), 15.f);
    float e = __expf(2.f * xc);
    return __fdividef(e - 1.f, e + 1.f);
}
// memory_lengths dtype sniff (int64 vs int32): word[1]==0 iff int64 (LE)
__device__ __forceinline__ int load_len(const void* lens, int b) {
    const int* p32 = (const int*)lens;
    if (p32[1] == 0) return (int)((const long long*)lens)[b];
    return p32[b];
}
__device__ __forceinline__ uint32_t smem_u32(const void* p) {
    uint32_t a;
    asm("{ .reg .u64 t; cvta.to.shared.u64 t, %1; cvt.u32.u64 %0, t; }" : "=r"(a) : "l"(p));
    return a;
}
__device__ __forceinline__ void cp_async16(uint32_t dst, const void* src) {
    asm volatile("cp.async.cg.shared.global [%0], [%1], 16;" :: "r"(dst), "l"(src));
}
__device__ __forceinline__ void mma_tf32(float* c, const uint32_t* a,
                                         uint32_t b0, uint32_t b1) {
    asm volatile(
        "mma.sync.aligned.m16n8k8.row.col.f32.tf32.tf32.f32 "
        "{%0,%1,%2,%3}, {%4,%5,%6,%7}, {%8,%9}, {%0,%1,%2,%3};"
        : "+f"(c[0]), "+f"(c[1]), "+f"(c[2]), "+f"(c[3])
        : "r"(a[0]), "r"(a[1]), "r"(a[2]), "r"(a[3]), "r"(b0), "r"(b1));
}

// ============================================================
// Kernel 0: prep Wc -> g_wcF (fragment order, tf32). grid 128, block 512.
// pack p: lane | j2 | wc | kk | kb ; floats = {je_b0, je_b1, jo_b0, jo_b1}
// ============================================================
__global__ void prep_wc_kernel(const float* __restrict__ Wc) {
    int p = blockIdx.x * 512 + threadIdx.x;
    int lane = p & 31;
    int j2   = (p >> 5) & 3;
    int wc   = (p >> 7) & 7;
    int kk   = (p >> 10) & 3;
    int kb   = (p >> 12) & 15;
    int g = lane >> 2, t = lane & 3;
    int e0 = wc * 64 + (j2 * 2) * 8 + g;
    int e1 = e0 + 8;
    int k0 = kb * 32 + kk * 8 + t;
    int k1 = k0 + 4;
    float4 f;
    f.x = to_tf32(Wc[(size_t)e0 * D_ + k0]);
    f.y = to_tf32(Wc[(size_t)e0 * D_ + k1]);
    f.z = to_tf32(Wc[(size_t)e1 * D_ + k0]);
    f.w = to_tf32(Wc[(size_t)e1 * D_ + k1]);
    ((float4*)g_wcF)[p] = f;
}

// ============================================================
// Kernel 1: wq = source @ Wq^T + bq.  grid (4, B), block 128
// ============================================================
__global__ void wq_kernel(const float* __restrict__ src,
                          const float* __restrict__ Wq,
                          const float* __restrict__ bq) {
    int b = blockIdx.y;
    int e = blockIdx.x * 128 + threadIdx.x;
    __shared__ __align__(16) float s_src[D_];
    for (int i = threadIdx.x; i < D_; i += 128) s_src[i] = src[b * D_ + i];
    __syncthreads();
    const float4* w4 = (const float4*)(Wq + (size_t)e * D_);
    const float4* s4 = (const float4*)s_src;
    float acc = 0.f;
#pragma unroll 8
    for (int i = 0; i < D_ / 4; ++i) {
        float4 wv = w4[i], xv = s4[i];
        acc += wv.x * xv.x + wv.y * xv.y + wv.z * xv.z + wv.w * xv.w;
    }
    g_wq[b * D_ + e] = acc + bq[e];
}

// ============================================================
// Kernel 2: fused scores. TM=128 rows x TN=256 cols per CTA.
// grid (32, B): x = sch*2 + nh (nh-pairs adjacent -> A L2 reuse). block 512.
// 16 warps = 4 wr x 4 wc; warp tile m32 x n64. tf32 mma, double-buffered.
// ============================================================
#define ASZ (TM * TK)               // 4096 floats per A buffer
#define OF_AS   0
#define OF_BS   (2 * ASZ)
#define OF_WQ   (OF_BS + 2 * HBSZ)
#define OF_V    (OF_WQ + TN)
#define OF_PART (OF_V + TN)
#define SMEM_FLOATS (OF_PART + TM * 4)
#define SMEM_BYTES  (SMEM_FLOATS * 4)

// A fragment float index for (row r in 0..127, k in 0..31)
__device__ __forceinline__ int a_frag_idx(int r, int k) {
    int kk = k >> 3, t = k & 3, k4 = (k >> 2) & 1;
    int wr = r >> 5, mt = (r >> 4) & 1, pm = (r >> 3) & 1, g = r & 7;
    return (((kk * 4 + wr) * 2 + mt) * 32 + (g * 4 + t)) * 4 + (k4 * 2 + pm);
}

__global__ void __launch_bounds__(512, 1)
scores_kernel(const float* __restrict__ mb, const float* __restrict__ vvec) {
    extern __shared__ __align__(16) float sm[];
    float* As    = sm + OF_AS;
    float* Bs    = sm + OF_BS;
    float* swq   = sm + OF_WQ;
    float* sv    = sm + OF_V;
    float* spart = sm + OF_PART;

    const int b   = blockIdx.y;
    const int nh  = blockIdx.x & 1;
    const int s0  = (blockIdx.x >> 1) * TM;
    const int tid = threadIdx.x;
    const int wid = tid >> 5, lane = tid & 31;
    const int g = lane >> 2, t = lane & 3;
    const int wr = wid >> 2, wc = wid & 3;      // 4 x 4 warps
    const int m0 = wr * 32;

    // this CTA's 256-col slice of wq and v
    for (int i = tid; i < TN; i += 512) {
        swq[i] = g_wq[b * D_ + nh * TN + i];
        sv[i]  = vvec[nh * TN + i];
    }

    // A staging indices: thread -> (row, 8 consecutive k)
    const int am   = tid >> 2;                 // row 0..127
    const int koff = (tid & 3) * 8;            // k offset 0..24
    const float* a_gbase = mb + (size_t)b * S_ * D_ + (size_t)(s0 + am) * D_ + koff;
    const uint32_t sbase = smem_u32(sm);
    int afi[8];
#pragma unroll
    for (int i = 0; i < 8; ++i) afi[i] = a_frag_idx(am, koff + i);

    float acc[2][8][4];
#pragma unroll
    for (int mt = 0; mt < 2; ++mt)
#pragma unroll
        for (int j = 0; j < 8; ++j)
#pragma unroll
            for (int q = 0; q < 4; ++q) acc[mt][j][q] = 0.f;

    // B copy helper indices: 2048 float4 per half-tile, 4 per thread
    // fi = tid + c*512 ; kk = fi>>9 ; rem = fi&511
    // src float4 = kb base + kk*1024 + nh*512 + rem ; dst float4 = fi
#define STAGE_B(kb_, buf_) do {                                              \
        const float4* bsrc4 = (const float4*)(g_wcF[kb_]);                   \
        uint32_t bdst = sbase + (OF_BS + (buf_) * HBSZ) * 4;                 \
        _Pragma("unroll")                                                    \
        for (int c = 0; c < 4; ++c) {                                        \
            int fi = tid + c * 512;                                          \
            int kk_ = fi >> 9, rem = fi & 511;                               \
            cp_async16(bdst + fi * 16, bsrc4 + kk_ * 1024 + nh * 512 + rem); \
        }                                                                    \
    } while (0)

    // ---- prologue: stage tile 0 ----
    {
        STAGE_B(0, 0);
        asm volatile("cp.async.commit_group;" ::: "memory");
        float4 av0 = *(const float4*)a_gbase;
        float4 av1 = *(const float4*)(a_gbase + 4);
        As[afi[0]] = to_tf32(av0.x); As[afi[1]] = to_tf32(av0.y);
        As[afi[2]] = to_tf32(av0.z); As[afi[3]] = to_tf32(av0.w);
        As[afi[4]] = to_tf32(av1.x); As[afi[5]] = to_tf32(av1.y);
        As[afi[6]] = to_tf32(av1.z); As[afi[7]] = to_tf32(av1.w);
    }

#pragma unroll 1
    for (int kb = 0; kb < NKT; ++kb) {
        const int cur = kb & 1;
        float4 av0, av1;
        if (kb < NKT - 1) {
            av0 = *(const float4*)(a_gbase + (kb + 1) * TK);
            av1 = *(const float4*)(a_gbase + (kb + 1) * TK + 4);
            STAGE_B(kb + 1, cur ^ 1);
            asm volatile("cp.async.commit_group;" ::: "memory");
            asm volatile("cp.async.wait_group 1;" ::: "memory");
        } else {
            asm volatile("cp.async.wait_group 0;" ::: "memory");
        }
        __syncthreads();

        const float* Ac = As + cur * ASZ;
        const float* Bc = Bs + cur * HBSZ;
#pragma unroll
        for (int kk = 0; kk < 4; ++kk) {
            uint32_t a[2][4];
#pragma unroll
            for (int mt = 0; mt < 2; ++mt) {
                float4 af = *(const float4*)(Ac + ((kk * 4 + wr) * 2 + mt) * 128 + lane * 4);
                a[mt][0] = __float_as_uint(af.x);
                a[mt][1] = __float_as_uint(af.y);
                a[mt][2] = __float_as_uint(af.z);
                a[mt][3] = __float_as_uint(af.w);
            }
            const float* brow = Bc + ((kk * 4 + wc) * 4) * 128 + lane * 4;
#pragma unroll
            for (int j2 = 0; j2 < 4; ++j2) {
                float4 bf = *(const float4*)(brow + j2 * 128);
                uint32_t b0 = __float_as_uint(bf.x), b1 = __float_as_uint(bf.y);
                uint32_t b2 = __float_as_uint(bf.z), b3 = __float_as_uint(bf.w);
                mma_tf32(acc[0][j2 * 2],     a[0], b0, b1);
                mma_tf32(acc[1][j2 * 2],     a[1], b0, b1);
                mma_tf32(acc[0][j2 * 2 + 1], a[0], b2, b3);
                mma_tf32(acc[1][j2 * 2 + 1], a[1], b2, b3);
            }
        }

        if (kb < NKT - 1) {
            float* Ad = As + (cur ^ 1) * ASZ;
            Ad[afi[0]] = to_tf32(av0.x); Ad[afi[1]] = to_tf32(av0.y);
            Ad[afi[2]] = to_tf32(av0.z); Ad[afi[3]] = to_tf32(av0.w);
            Ad[afi[4]] = to_tf32(av1.x); Ad[afi[5]] = to_tf32(av1.y);
            Ad[afi[6]] = to_tf32(av1.z); Ad[afi[7]] = to_tf32(av1.w);
        }
        __syncthreads();
    }

    // ---- epilogue: tanh + v dot over this CTA's 256 cols ----
    float p[4] = {0.f, 0.f, 0.f, 0.f};
#pragma unroll
    for (int mt = 0; mt < 2; ++mt)
#pragma unroll
        for (int j = 0; j < 8; ++j) {
            const int c = wc * 64 + j * 8 + 2 * t;     // local col
            const float v0 = sv[c], v1 = sv[c + 1];
            const float w0 = swq[c], w1 = swq[c + 1];
            p[mt * 2 + 0] += fast_tanh(w0 + acc[mt][j][0]) * v0 +
                             fast_tanh(w1 + acc[mt][j][1]) * v1;
            p[mt * 2 + 1] += fast_tanh(w0 + acc[mt][j][2]) * v0 +
                             fast_tanh(w1 + acc[mt][j][3]) * v1;
        }
#pragma unroll
    for (int q = 0; q < 4; ++q) {
        p[q] += __shfl_xor_sync(0xFFFFFFFFu, p[q], 1);
        p[q] += __shfl_xor_sync(0xFFFFFFFFu, p[q], 2);
    }
    if (t == 0) {
#pragma unroll
        for (int mt = 0; mt < 2; ++mt) {
            spart[(m0 + mt * 16 + g) * 4 + wc]     = p[mt * 2 + 0];
            spart[(m0 + mt * 16 + g + 8) * 4 + wc] = p[mt * 2 + 1];
        }
    }
    __syncthreads();
    if (tid < TM) {
        float s = spart[tid * 4] + spart[tid * 4 + 1] +
                  spart[tid * 4 + 2] + spart[tid * 4 + 3];
        g_spart[nh][b * S_ + s0 + tid] = s;
    }
}

// ============================================================
// Kernel 3: combine partials + masked softmax stats. grid B, block 1024
// ============================================================
__global__ void stats_kernel(const void* __restrict__ lens) {
    __shared__ float sc[S_];
    __shared__ float red[1024];
    int b = blockIdx.x, tid = threadIdx.x;
    int len = load_len(lens, b);

    for (int s = tid; s < S_; s += 1024) {
        float v = g_spart[0][b * S_ + s] + g_spart[1][b * S_ + s];
        sc[s] = v;
        g_scores[b * S_ + s] = v;
    }
    __syncthreads();

    float m = -3.4e38f;
    for (int s = tid; s < S_; s += 1024)
        if (s < len) m = fmaxf(m, sc[s]);
    red[tid] = m;
    __syncthreads();
    for (int o = 512; o > 0; o >>= 1) {
        if (tid < o) red[tid] = fmaxf(red[tid], red[tid + o]);
        __syncthreads();
    }
    m = red[0];
    __syncthreads();

    float sum = 0.f;
    for (int s = tid; s < S_; s += 1024)
        if (s < len) sum += __expf(sc[s] - m);
    red[tid] = sum;
    __syncthreads();
    for (int o = 512; o > 0; o >>= 1) {
        if (tid < o) red[tid] += red[tid + o];
        __syncthreads();
    }
    if (tid == 0) { g_stats[2 * b] = m; g_stats[2 * b + 1] = red[0]; }
}

// ============================================================
// Kernel 4a: context partials. grid (32, B): x = dch(4) + 4*sch(8). block 128
// ============================================================
__global__ void context_part_kernel(const float* __restrict__ mb,
                                    const void* __restrict__ lens,
                                    float* __restrict__ out) {
    __shared__ float w[256];
    int b = blockIdx.y, tid = threadIdx.x;
    int dch = blockIdx.x & 3, sch = blockIdx.x >> 2;
    int len = load_len(lens, b);
    float m = g_stats[2 * b];
    float inv = __fdividef(1.f, g_stats[2 * b + 1]);

    int sbase = sch * 256;
    for (int i = tid; i < 256; i += 128) {
        int s = sbase + i;
        w[i] = (s < len) ? __expf(g_scores[b * S_ + s] - m) * inv : 0.f;
    }
    __syncthreads();

    if (dch == 0) {
        float* align_out = out + B_ * D_;
        for (int i = tid; i < 256; i += 128) align_out[b * S_ + sbase + i] = w[i];
    }

    int d = dch * 128 + tid;
    const float* p = mb + (size_t)b * S_ * D_ + (size_t)sbase * D_ + d;
    float acc = 0.f;
#pragma unroll 8
    for (int i = 0; i < 256; ++i) acc += w[i] * p[(size_t)i * D_];
    g_ctx[sch][b * D_ + d] = acc;
}

// ============================================================
// Kernel 4b: combine context partials. grid B, block 128
// ============================================================
__global__ void combine_kernel(float* __restrict__ out) {
    int b = blockIdx.x, tid = threadIdx.x;
    for (int d = tid; d < D_; d += 128) {
        int i = b * D_ + d;
        float s = 0.f;
#pragma unroll
        for (int c = 0; c < NSCH; ++c) s += g_ctx[c][i];
        out[i] = s;
    }
}

// ============================================================
extern "C" void kernel_launch(void* const* d_in, const int* in_sizes, int n_in,
                              void* d_out, int out_size) {
    const float* source = (const float*)d_in[0];
    const float* mb     = (const float*)d_in[1];
    const void*  lens   = (const void*)d_in[2];
    const float* Wq     = (const float*)d_in[3];
    const float* bq     = (const float*)d_in[4];
    const float* Wc     = (const float*)d_in[5];
    const float* v      = (const float*)d_in[6];
    float*       out    = (float*)d_out;

    cudaFuncSetAttribute(scores_kernel,
                         cudaFuncAttributeMaxDynamicSharedMemorySize, SMEM_BYTES);

    prep_wc_kernel<<<128, 512>>>(Wc);
    wq_kernel<<<dim3(4, B_), 128>>>(source, Wq, bq);
    scores_kernel<<<dim3((S_ / TM) * 2, B_), 512, SMEM_BYTES>>>(mb, v);
    stats_kernel<<<B_, 1024>>>(lens);
    context_part_kernel<<<dim3(32, B_), 128>>>(mb, lens, out);
    combine_kernel<<<B_, 128>>>(out);
}

// round 7
// speedup vs baseline: 1.9310x; 1.9310x over previous
#include <cuda_runtime.h>
#include <cuda_fp16.h>
#include <cstdint>

#define B_ 64
#define S_ 2048
#define D_ 512

#define TM 64            // M rows per CTA
#define TK 32            // K per stage tile
#define NKT (D_ / TK)    // 16 k-tiles
#define NSCH 8           // context S-chunks

// ---------------- scratch globals ----------------
__device__ float g_wq[B_ * D_];
__device__ float g_scores[B_ * S_];
__device__ float g_stats[2 * B_];
__device__ float g_ctx[NSCH][B_ * D_];
// Wc as fp16 in m16n8k16-fragment order: uint4 index = kb<<11 | kk<<10 | wc<<7 | j2<<5 | lane
__device__ __align__(16) uint4 g_wcH[NKT * 2048];

// ---------------- helpers ----------------
__device__ __forceinline__ float fast_tanh(float x) {
    float xc = fminf(fmaxf(x, -15.f), 15.f);
    float e = __expf(2.f * xc);
    return __fdividef(e - 1.f, e + 1.f);
}
// memory_lengths dtype sniff (int64 vs int32): word[1]==0 iff int64 (LE)
__device__ __forceinline__ int load_len(const void* lens, int b) {
    const int* p32 = (const int*)lens;
    if (p32[1] == 0) return (int)((const long long*)lens)[b];
    return p32[b];
}
__device__ __forceinline__ uint32_t smem_u32(const void* p) {
    uint32_t a;
    asm("{ .reg .u64 t; cvta.to.shared.u64 t, %1; cvt.u32.u64 %0, t; }" : "=r"(a) : "l"(p));
    return a;
}
__device__ __forceinline__ void cp_async16(uint32_t dst, const void* src) {
    asm volatile("cp.async.cg.shared.global [%0], [%1], 16;" :: "r"(dst), "l"(src));
}
__device__ __forceinline__ uint32_t packh2(float a, float b) {
    __half2 h = __floats2half2_rn(a, b);
    return *(uint32_t*)&h;
}
__device__ __forceinline__ void mma_fp16(float* c, const uint32_t* a,
                                         uint32_t b0, uint32_t b1) {
    asm volatile(
        "mma.sync.aligned.m16n8k16.row.col.f32.f16.f16.f32 "
        "{%0,%1,%2,%3}, {%4,%5,%6,%7}, {%8,%9}, {%0,%1,%2,%3};"
        : "+f"(c[0]), "+f"(c[1]), "+f"(c[2]), "+f"(c[3])
        : "r"(a[0]), "r"(a[1]), "r"(a[2]), "r"(a[3]), "r"(b0), "r"(b1));
}

// ============================================================
// Kernel 0: prep Wc -> g_wcH (fp16, m16n8k16 B-fragment order). grid 64, block 512.
// uint4 p: x={B[k0][ne],B[k0+1][ne]} y={B[k0+8][ne],B[k0+9][ne]} z,w same for no
// where B[k][n] = Wc[n*D+k]
// ============================================================
__global__ void prep_wc_kernel(const float* __restrict__ Wc) {
    int p = blockIdx.x * 512 + threadIdx.x;     // 32768 uint4
    int lane = p & 31;
    int j2   = (p >> 5) & 3;
    int wc   = (p >> 7) & 7;
    int kk   = (p >> 10) & 1;
    int kb   = (p >> 11) & 15;
    int g = lane >> 2, t = lane & 3;
    int ne = wc * 64 + j2 * 16 + g;
    int no = ne + 8;
    int k0 = kb * 32 + kk * 16 + 2 * t;
    const float* we = Wc + (size_t)ne * D_;
    const float* wo = Wc + (size_t)no * D_;
    uint4 f;
    f.x = packh2(we[k0],     we[k0 + 1]);
    f.y = packh2(we[k0 + 8], we[k0 + 9]);
    f.z = packh2(wo[k0],     wo[k0 + 1]);
    f.w = packh2(wo[k0 + 8], wo[k0 + 9]);
    g_wcH[p] = f;
}

// ============================================================
// Kernel 1: wq = source @ Wq^T + bq.  grid (4, B), block 128
// ============================================================
__global__ void wq_kernel(const float* __restrict__ src,
                          const float* __restrict__ Wq,
                          const float* __restrict__ bq) {
    int b = blockIdx.y;
    int e = blockIdx.x * 128 + threadIdx.x;
    __shared__ __align__(16) float s_src[D_];
    for (int i = threadIdx.x; i < D_; i += 128) s_src[i] = src[b * D_ + i];
    __syncthreads();
    const float4* w4 = (const float4*)(Wq + (size_t)e * D_);
    const float4* s4 = (const float4*)s_src;
    float acc = 0.f;
#pragma unroll 8
    for (int i = 0; i < D_ / 4; ++i) {
        float4 wv = w4[i], xv = s4[i];
        acc += wv.x * xv.x + wv.y * xv.y + wv.z * xv.z + wv.w * xv.w;
    }
    g_wq[b * D_ + e] = acc + bq[e];
}

// ============================================================
// Kernel 2: fused scores, fp16 m16n8k16, fragment-packed operands,
// cp.async double-buffered. grid (S/64, B), block 512 (2wr x 8wc).
// Warp tile m32 x n64, full N=512 in fp32 accumulators.
// ============================================================
#define A_U32 1024                  // uint32 per A buffer (64 rows x 32 k fp16)
#define B_U32 8192                  // uint32 per B buffer (32 k x 512 e fp16)
#define OF_AS   0
#define OF_BS   (2 * A_U32)
#define OF_WQ   (OF_BS + 2 * B_U32)
#define OF_V    (OF_WQ + D_)
#define OF_PART (OF_V + D_)
#define SMEM_U32 (OF_PART + TM * 8)
#define SMEM_BYTES (SMEM_U32 * 4)

__global__ void __launch_bounds__(512, 1)
scores_kernel(const float* __restrict__ mb, const float* __restrict__ vvec) {
    extern __shared__ __align__(16) uint32_t sm[];
    uint32_t* As = sm + OF_AS;
    float* swq   = (float*)(sm + OF_WQ);
    float* sv    = (float*)(sm + OF_V);
    float* spart = (float*)(sm + OF_PART);

    const int b   = blockIdx.y;
    const int s0  = blockIdx.x * TM;
    const int tid = threadIdx.x;
    const int wid = tid >> 5, lane = tid & 31;
    const int g = lane >> 2, t = lane & 3;
    const int wr = wid >> 3, wc = wid & 7;
    const int m0 = wr * 32, n0 = wc * 64;

    for (int i = tid; i < D_; i += 512) {
        swq[i] = g_wq[b * D_ + i];
        sv[i]  = vvec[i];
    }

    // A staging: thread -> (row = tid>>3, 4 k at koff=(tid&7)*4) -> 2 fp16x2 stores
    const int am   = tid >> 3;
    const int koff = (tid & 7) * 4;
    const float* a_gbase = mb + (size_t)b * S_ * D_ + (size_t)(s0 + am) * D_ + koff;
    const uint32_t sbase = smem_u32(sm);
    int i0;
    {
        int kk = koff >> 4;
        int tt = (koff & 7) >> 1;          // 0 or 2
        int kq = (koff & 15) >> 3;
        int gg = am & 7, pm = (am >> 3) & 1, awr = (am >> 5) & 1, mt = (am >> 4) & 1;
        i0 = ((kk * 2 + awr) * 2 + mt) * 128 + (gg * 4 + tt) * 4 + (kq * 2 + pm);
    }

    float acc[2][8][4];
#pragma unroll
    for (int mt = 0; mt < 2; ++mt)
#pragma unroll
        for (int j = 0; j < 8; ++j)
#pragma unroll
            for (int q = 0; q < 4; ++q) acc[mt][j][q] = 0.f;

#define STAGE_B(kb_, buf_) do {                                            \
        const uint4* bsrc4 = g_wcH + (kb_) * 2048;                         \
        uint32_t bdst = sbase + (OF_BS + (buf_) * B_U32) * 4;              \
        _Pragma("unroll")                                                  \
        for (int c = 0; c < 4; ++c) {                                      \
            int fi = tid + c * 512;                                        \
            cp_async16(bdst + fi * 16, bsrc4 + fi);                        \
        }                                                                  \
    } while (0)

    // ---- prologue: stage tile 0 ----
    {
        STAGE_B(0, 0);
        asm volatile("cp.async.commit_group;" ::: "memory");
        float4 av = *(const float4*)a_gbase;
        As[i0]     = packh2(av.x, av.y);
        As[i0 + 4] = packh2(av.z, av.w);
    }

#pragma unroll 1
    for (int kb = 0; kb < NKT; ++kb) {
        const int cur = kb & 1;
        float4 av;
        if (kb < NKT - 1) {
            av = *(const float4*)(a_gbase + (kb + 1) * TK);
            STAGE_B(kb + 1, cur ^ 1);
            asm volatile("cp.async.commit_group;" ::: "memory");
            asm volatile("cp.async.wait_group 1;" ::: "memory");
        } else {
            asm volatile("cp.async.wait_group 0;" ::: "memory");
        }
        __syncthreads();

        const uint32_t* Ac = As + cur * A_U32;
        const uint4* Bc = (const uint4*)(sm + OF_BS + cur * B_U32);
#pragma unroll
        for (int kk = 0; kk < 2; ++kk) {
            uint32_t a[2][4];
#pragma unroll
            for (int mt = 0; mt < 2; ++mt) {
                uint4 af = *(const uint4*)(Ac + ((kk * 2 + wr) * 2 + mt) * 128 + lane * 4);
                a[mt][0] = af.x; a[mt][1] = af.y; a[mt][2] = af.z; a[mt][3] = af.w;
            }
            const uint4* brow = Bc + ((kk * 8 + wc) * 4) * 32 + lane;
#pragma unroll
            for (int j2 = 0; j2 < 4; ++j2) {
                uint4 bf = brow[j2 * 32];
                mma_fp16(acc[0][j2 * 2],     a[0], bf.x, bf.y);
                mma_fp16(acc[1][j2 * 2],     a[1], bf.x, bf.y);
                mma_fp16(acc[0][j2 * 2 + 1], a[0], bf.z, bf.w);
                mma_fp16(acc[1][j2 * 2 + 1], a[1], bf.z, bf.w);
            }
        }

        if (kb < NKT - 1) {
            uint32_t* Ad = As + (cur ^ 1) * A_U32;
            Ad[i0]     = packh2(av.x, av.y);
            Ad[i0 + 4] = packh2(av.z, av.w);
        }
        __syncthreads();
    }

    // ---- epilogue: tanh + v dot, reduce ----
    float p[4] = {0.f, 0.f, 0.f, 0.f};
#pragma unroll
    for (int mt = 0; mt < 2; ++mt)
#pragma unroll
        for (int j = 0; j < 8; ++j) {
            const int c = n0 + j * 8 + 2 * t;
            const float v0 = sv[c], v1 = sv[c + 1];
            const float w0 = swq[c], w1 = swq[c + 1];
            p[mt * 2 + 0] += fast_tanh(w0 + acc[mt][j][0]) * v0 +
                             fast_tanh(w1 + acc[mt][j][1]) * v1;
            p[mt * 2 + 1] += fast_tanh(w0 + acc[mt][j][2]) * v0 +
                             fast_tanh(w1 + acc[mt][j][3]) * v1;
        }
#pragma unroll
    for (int q = 0; q < 4; ++q) {
        p[q] += __shfl_xor_sync(0xFFFFFFFFu, p[q], 1);
        p[q] += __shfl_xor_sync(0xFFFFFFFFu, p[q], 2);
    }
    if (t == 0) {
#pragma unroll
        for (int mt = 0; mt < 2; ++mt) {
            spart[(m0 + mt * 16 + g) * 8 + wc]     = p[mt * 2 + 0];
            spart[(m0 + mt * 16 + g + 8) * 8 + wc] = p[mt * 2 + 1];
        }
    }
    __syncthreads();
    if (tid < TM) {
        float s = 0.f;
#pragma unroll
        for (int w = 0; w < 8; ++w) s += spart[tid * 8 + w];
        g_scores[b * S_ + s0 + tid] = s;
    }
}

// ============================================================
// Kernel 3: masked softmax stats. grid B, block 1024
// ============================================================
__global__ void stats_kernel(const void* __restrict__ lens) {
    __shared__ float red[1024];
    int b = blockIdx.x, tid = threadIdx.x;
    int len = load_len(lens, b);

    float m = -3.4e38f;
    for (int s = tid; s < S_; s += 1024)
        if (s < len) m = fmaxf(m, g_scores[b * S_ + s]);
    red[tid] = m;
    __syncthreads();
    for (int o = 512; o > 0; o >>= 1) {
        if (tid < o) red[tid] = fmaxf(red[tid], red[tid + o]);
        __syncthreads();
    }
    m = red[0];
    __syncthreads();

    float sum = 0.f;
    for (int s = tid; s < S_; s += 1024)
        if (s < len) sum += __expf(g_scores[b * S_ + s] - m);
    red[tid] = sum;
    __syncthreads();
    for (int o = 512; o > 0; o >>= 1) {
        if (tid < o) red[tid] += red[tid + o];
        __syncthreads();
    }
    if (tid == 0) { g_stats[2 * b] = m; g_stats[2 * b + 1] = red[0]; }
}

// ============================================================
// Kernel 4a: context partials. grid (32, B): x = dch(4) + 4*sch(8). block 128
// ============================================================
__global__ void context_part_kernel(const float* __restrict__ mb,
                                    const void* __restrict__ lens,
                                    float* __restrict__ out) {
    __shared__ float w[256];
    int b = blockIdx.y, tid = threadIdx.x;
    int dch = blockIdx.x & 3, sch = blockIdx.x >> 2;
    int len = load_len(lens, b);
    float m = g_stats[2 * b];
    float inv = __fdividef(1.f, g_stats[2 * b + 1]);

    int sbase = sch * 256;
    for (int i = tid; i < 256; i += 128) {
        int s = sbase + i;
        w[i] = (s < len) ? __expf(g_scores[b * S_ + s] - m) * inv : 0.f;
    }
    __syncthreads();

    if (dch == 0) {
        float* align_out = out + B_ * D_;
        for (int i = tid; i < 256; i += 128) align_out[b * S_ + sbase + i] = w[i];
    }

    int d = dch * 128 + tid;
    const float* p = mb + (size_t)b * S_ * D_ + (size_t)sbase * D_ + d;
    float acc = 0.f;
#pragma unroll 8
    for (int i = 0; i < 256; ++i) acc += w[i] * p[(size_t)i * D_];
    g_ctx[sch][b * D_ + d] = acc;
}

// ============================================================
// Kernel 4b: combine context partials. grid B, block 128
// ============================================================
__global__ void combine_kernel(float* __restrict__ out) {
    int b = blockIdx.x, tid = threadIdx.x;
    for (int d = tid; d < D_; d += 128) {
        int i = b * D_ + d;
        float s = 0.f;
#pragma unroll
        for (int c = 0; c < NSCH; ++c) s += g_ctx[c][i];
        out[i] = s;
    }
}

// ============================================================
extern "C" void kernel_launch(void* const* d_in, const int* in_sizes, int n_in,
                              void* d_out, int out_size) {
    const float* source = (const float*)d_in[0];
    const float* mb     = (const float*)d_in[1];
    const void*  lens   = (const void*)d_in[2];
    const float* Wq     = (const float*)d_in[3];
    const float* bq     = (const float*)d_in[4];
    const float* Wc     = (const float*)d_in[5];
    const float* v      = (const float*)d_in[6];
    float*       out    = (float*)d_out;

    cudaFuncSetAttribute(scores_kernel,
                         cudaFuncAttributeMaxDynamicSharedMemorySize, SMEM_BYTES);

    prep_wc_kernel<<<64, 512>>>(Wc);
    wq_kernel<<<dim3(4, B_), 128>>>(source, Wq, bq);
    scores_kernel<<<dim3(S_ / TM, B_), 512, SMEM_BYTES>>>(mb, v);
    stats_kernel<<<B_, 1024>>>(lens);
    context_part_kernel<<<dim3(32, B_), 128>>>(mb, lens, out);
    combine_kernel<<<B_, 128>>>(out);
}